// round 4
// baseline (speedup 1.0000x reference)
#include <cuda_runtime.h>
#include <math.h>

// Problem constants
#define BB   64
#define NN   100
#define LL   32
#define RR   (BB*NN)     // 6400 rows
#define EH   64          // edge hidden / edge out width
#define NHID 64          // node hidden
#define NOUT 32          // node out (== LL, d stays 32)
#define ALPHA 0.1f

// Scratch (static device globals — no allocations allowed)
__device__ float g_h   [RR*LL];        // node features (updated in place per step)
__device__ float g_s   [RR*EH];        // u_i + b0  (layer-0 "i" part)
__device__ float g_v   [RR*EH];        // v_j       (layer-0 "j" part)
__device__ float g_dist[BB*NN*NN];     // pairwise distances per batch
__device__ float g_agg [RR*EH];        // sum_j A[b,i,j,:]

__device__ __forceinline__ float lrelu(float x) { return x > 0.f ? x : ALPHA * x; }

// ---------------------------------------------------------------------------
// h = (x @ lin_w + lin_b).reshape(B, N, L)   — one block per batch element
// ---------------------------------------------------------------------------
__global__ void k_lin(const float* __restrict__ x,
                      const float* __restrict__ w,
                      const float* __restrict__ b)
{
    __shared__ float xs[LL];
    const int bb = blockIdx.x;
    if (threadIdx.x < LL) xs[threadIdx.x] = x[bb*LL + threadIdx.x];
    __syncthreads();
    for (int col = threadIdx.x; col < NN*LL; col += blockDim.x) {
        float acc = b[col];
        #pragma unroll
        for (int k = 0; k < LL; k++)
            acc += xs[k] * w[k*(NN*LL) + col];
        g_h[bb*NN*LL + col] = acc;
    }
}

// ---------------------------------------------------------------------------
// Per-step prep: s[r][c] = b0[c] + sum_k h[r][k]*W0[k][c]       (xi part)
//                v[r][c] =         sum_k h[r][k]*W0[32+k][c]    (xj part)
// one block per row, 64 threads
// ---------------------------------------------------------------------------
__global__ void k_prep(const float* __restrict__ w0,
                       const float* __restrict__ b0)
{
    const int r = blockIdx.x;
    const int c = threadIdx.x;  // 0..63
    __shared__ float hs[LL];
    if (c < LL) hs[c] = g_h[r*LL + c];
    __syncthreads();
    float su = b0[c], sv = 0.f;
    #pragma unroll
    for (int k = 0; k < LL; k++) {
        const float hk = hs[k];
        su += hk * w0[k*EH + c];
        sv += hk * w0[(LL + k)*EH + c];
    }
    g_s[r*EH + c] = su;
    g_v[r*EH + c] = sv;
}

// ---------------------------------------------------------------------------
// Pairwise distances: dist[b,i,j] = sqrt(||h_i - h_j||^2 + 1e-12)
// grid = 64 batches x 4 i-chunks of 25, 256 threads
// ---------------------------------------------------------------------------
__global__ void k_dist()
{
    const int bb    = blockIdx.x >> 2;
    const int chunk = blockIdx.x & 3;
    __shared__ float hs[NN*LL];
    for (int idx = threadIdx.x; idx < NN*LL; idx += blockDim.x)
        hs[idx] = g_h[bb*NN*LL + idx];
    __syncthreads();
    const int i0 = chunk * 25;
    for (int idx = threadIdx.x; idx < 25*NN; idx += blockDim.x) {
        const int i = i0 + idx / NN;
        const int j = idx % NN;
        const float* hi = &hs[i*LL];
        const float* hj = &hs[j*LL];
        float d2 = 1e-12f;
        #pragma unroll
        for (int k = 0; k < LL; k++) {
            const float dk = hi[k] - hj[k];
            d2 += dk * dk;
        }
        g_dist[bb*NN*NN + i*NN + j] = sqrtf(d2);
    }
}

// ---------------------------------------------------------------------------
// Edge MLP + aggregation — the hot kernel.
// One block per (b,i). Phase 1 builds t[k][j] = leaky(s_i + v_j + dist*wd)
// for all 100 j. Phase 2 is a register-tiled (100 x 64)@(64 x 64) GEMM with
// fused leaky-relu + sum-over-j epilogue.
//   blockDim = 128: cg = tid&7 owns 8 output cols (2x float4), jg = tid>>3
//   strides over j by 16. Partial agg reduced through smem at the end.
// ---------------------------------------------------------------------------
#define TPAD 101   // stride for sh_t rows: 101 % 32 = 5, gcd(5,32)=1 -> conflict-free

__global__ void __launch_bounds__(128) k_edge(const float* __restrict__ w0,
                                              const float* __restrict__ w1,
                                              const float* __restrict__ b1)
{
    __shared__ float sh_t [EH * TPAD];   // t transposed: [k][j], 25.9 KB
    __shared__ float sh_w1[EH * EH];     // W1 [k][c], 16 KB
    __shared__ float sh_dist[NN];
    __shared__ float sh_s[EH], sh_wd[EH], sh_b1[EH];

    const int tid = threadIdx.x;
    const int r   = blockIdx.x;          // b*100 + i
    const int bb  = r / NN;
    const int i   = r - bb*NN;

    for (int idx = tid; idx < EH*EH; idx += 128) sh_w1[idx] = w1[idx];
    if (tid < NN) sh_dist[tid] = g_dist[bb*NN*NN + i*NN + tid];
    if (tid < EH) {
        sh_s [tid] = g_s[r*EH + tid];
        sh_wd[tid] = w0[(2*LL)*EH + tid];   // row 64 of W0: dist weights
        sh_b1[tid] = b1[tid];
    }
    __syncthreads();

    // Phase 1: layer-0 activations for all j (t stored k-major)
    const float* vbase = &g_v[bb*NN*EH];
    for (int idx = tid; idx < NN*EH; idx += 128) {
        const int j = idx >> 6;
        const int c = idx & 63;
        const float t = sh_s[c] + vbase[idx] + sh_dist[j] * sh_wd[c];
        sh_t[c*TPAD + j] = lrelu(t);
    }
    __syncthreads();

    // Phase 2: layer-1 GEMV per j, fused leaky + accumulate over j
    const int cg = tid & 7;     // 8 col-groups of 8
    const int c0 = cg * 8;
    const int jg = tid >> 3;    // 16 j-groups

    float acc[8];
    #pragma unroll
    for (int u = 0; u < 8; u++) acc[u] = 0.f;

    for (int j = jg; j < NN; j += 16) {
        float z[8];
        #pragma unroll
        for (int u = 0; u < 8; u++) z[u] = sh_b1[c0 + u];
        #pragma unroll 8
        for (int k = 0; k < EH; k++) {
            const float tk = sh_t[k*TPAD + j];
            const float4* wrow = reinterpret_cast<const float4*>(&sh_w1[k*EH + c0]);
            const float4 wa = wrow[0];
            const float4 wb = wrow[1];
            z[0] += tk * wa.x; z[1] += tk * wa.y; z[2] += tk * wa.z; z[3] += tk * wa.w;
            z[4] += tk * wb.x; z[5] += tk * wb.y; z[6] += tk * wb.z; z[7] += tk * wb.w;
        }
        #pragma unroll
        for (int u = 0; u < 8; u++) acc[u] += lrelu(z[u]);
    }

    // Reduce the 16 jg partials (reuse sh_t storage — t is dead now)
    __syncthreads();
    float* red = sh_t;                   // needs 16*64 floats, fits
    #pragma unroll
    for (int u = 0; u < 8; u++) red[jg*64 + c0 + u] = acc[u];
    __syncthreads();
    if (tid < EH) {
        float s = 0.f;
        #pragma unroll
        for (int g = 0; g < 16; g++) s += red[g*64 + tid];
        g_agg[r*EH + tid] = s;
    }
}

// ---------------------------------------------------------------------------
// Node MLP: h <- leaky(leaky([h, agg] @ Wn0 + bn0) @ Wn1 + bn1)
// one block per row, 64 threads; in-place update of g_h is safe (row-local)
// ---------------------------------------------------------------------------
__global__ void k_node(const float* __restrict__ wn0, const float* __restrict__ bn0,
                       const float* __restrict__ wn1, const float* __restrict__ bn1)
{
    const int r = blockIdx.x;
    const int c = threadIdx.x;   // 0..63
    __shared__ float in[LL + EH];   // 96
    __shared__ float hid[NHID];
    if (c < LL) in[c] = g_h[r*LL + c];
    in[LL + c] = g_agg[r*EH + c];
    __syncthreads();
    float a = bn0[c];
    #pragma unroll
    for (int k = 0; k < LL + EH; k++)
        a += in[k] * wn0[k*NHID + c];
    hid[c] = lrelu(a);
    __syncthreads();
    if (c < NOUT) {
        float o = bn1[c];
        #pragma unroll
        for (int k = 0; k < NHID; k++)
            o += hid[k] * wn1[k*NOUT + c];
        g_h[r*LL + c] = lrelu(o);
    }
}

// ---------------------------------------------------------------------------
// Output head: out = tanh(h @ out_w + out_b), shape (B*N, 3)
// ---------------------------------------------------------------------------
__global__ void k_out(const float* __restrict__ w,
                      const float* __restrict__ b,
                      float* __restrict__ out)
{
    const int idx = blockIdx.x * blockDim.x + threadIdx.x;
    if (idx >= RR * 3) return;
    const int r = idx / 3;
    const int o = idx - r*3;
    const float* h = &g_h[r*LL];
    float a = b[o];
    #pragma unroll
    for (int k = 0; k < LL; k++)
        a += h[k] * w[k*3 + o];
    out[idx] = tanhf(a);
}

// ---------------------------------------------------------------------------
// Launch — pure kernel launches, graph-capturable, allocation-free
// ---------------------------------------------------------------------------
extern "C" void kernel_launch(void* const* d_in, const int* in_sizes, int n_in,
                              void* d_out, int out_size)
{
    const float* x  = (const float*)d_in[0];
    const float* lw = (const float*)d_in[1];
    const float* lb = (const float*)d_in[2];
    const float* ew0[2] = { (const float*)d_in[3],  (const float*)d_in[11] };
    const float* eb0[2] = { (const float*)d_in[4],  (const float*)d_in[12] };
    const float* ew1[2] = { (const float*)d_in[5],  (const float*)d_in[13] };
    const float* eb1[2] = { (const float*)d_in[6],  (const float*)d_in[14] };
    const float* nw0[2] = { (const float*)d_in[7],  (const float*)d_in[15] };
    const float* nb0[2] = { (const float*)d_in[8],  (const float*)d_in[16] };
    const float* nw1[2] = { (const float*)d_in[9],  (const float*)d_in[17] };
    const float* nb1[2] = { (const float*)d_in[10], (const float*)d_in[18] };
    const float* ow = (const float*)d_in[19];
    const float* ob = (const float*)d_in[20];

    k_lin<<<BB, 256>>>(x, lw, lb);
    for (int s = 0; s < 2; s++) {
        k_prep<<<RR, 64>>>(ew0[s], eb0[s]);
        k_dist<<<BB*4, 256>>>();
        k_edge<<<RR, 128>>>(ew0[s], ew1[s], eb1[s]);
        k_node<<<RR, 64>>>(nw0[s], nb0[s], nw1[s], nb1[s]);
    }
    k_out<<<(RR*3 + 255)/256, 256>>>(ow, ob, (float*)d_out);
}

// round 8
// speedup vs baseline: 2.8696x; 2.8696x over previous
#include <cuda_runtime.h>
#include <math.h>

// Problem constants
#define BB   64
#define NN   100
#define LL   32
#define RR   (BB*NN)     // 6400 rows
#define EH   64          // edge hidden / edge out width
#define NHID 64          // node hidden
#define NOUT 32          // node out (== LL, d stays 32)
#define ALPHA 0.1f

// Scratch (static device globals — no allocations allowed)
__device__ float g_h   [RR*LL];        // node features (updated in place per step)
__device__ float g_s   [RR*EH];        // u_i + b0  (layer-0 "i" part)
__device__ float g_v   [RR*EH];        // v_j       (layer-0 "j" part)
__device__ float g_dist[BB*NN*NN];     // pairwise distances per batch
__device__ float g_agg [RR*EH];        // sum_j A[b,i,j,:]

__device__ __forceinline__ float lrelu(float x) { return x > 0.f ? x : ALPHA * x; }

// ---------------------------------------------------------------------------
// h = (x @ lin_w + lin_b).reshape(B, N, L)   — one block per batch element
// ---------------------------------------------------------------------------
__global__ void k_lin(const float* __restrict__ x,
                      const float* __restrict__ w,
                      const float* __restrict__ b)
{
    __shared__ float xs[LL];
    const int bb = blockIdx.x;
    if (threadIdx.x < LL) xs[threadIdx.x] = x[bb*LL + threadIdx.x];
    __syncthreads();
    for (int col = threadIdx.x; col < NN*LL; col += blockDim.x) {
        float acc = b[col];
        #pragma unroll
        for (int k = 0; k < LL; k++)
            acc += xs[k] * w[k*(NN*LL) + col];
        g_h[bb*NN*LL + col] = acc;
    }
}

// ---------------------------------------------------------------------------
// Per-step prep: s[r][c] = b0[c] + sum_k h[r][k]*W0[k][c]       (xi part)
//                v[r][c] =         sum_k h[r][k]*W0[32+k][c]    (xj part)
// ---------------------------------------------------------------------------
__global__ void k_prep(const float* __restrict__ w0,
                       const float* __restrict__ b0)
{
    const int r = blockIdx.x;
    const int c = threadIdx.x;  // 0..63
    __shared__ float hs[LL];
    if (c < LL) hs[c] = g_h[r*LL + c];
    __syncthreads();
    float su = b0[c], sv = 0.f;
    #pragma unroll
    for (int k = 0; k < LL; k++) {
        const float hk = hs[k];
        su += hk * w0[k*EH + c];
        sv += hk * w0[(LL + k)*EH + c];
    }
    g_s[r*EH + c] = su;
    g_v[r*EH + c] = sv;
}

// ---------------------------------------------------------------------------
// Pairwise distances: dist[b,i,j] = sqrt(||h_i - h_j||^2 + 1e-12)
// ---------------------------------------------------------------------------
__global__ void k_dist()
{
    const int bb    = blockIdx.x >> 2;
    const int chunk = blockIdx.x & 3;
    __shared__ float hs[NN*LL];
    for (int idx = threadIdx.x; idx < NN*LL; idx += blockDim.x)
        hs[idx] = g_h[bb*NN*LL + idx];
    __syncthreads();
    const int i0 = chunk * 25;
    for (int idx = threadIdx.x; idx < 25*NN; idx += blockDim.x) {
        const int i = i0 + idx / NN;
        const int j = idx % NN;
        const float* hi = &hs[i*LL];
        const float* hj = &hs[j*LL];
        float d2 = 1e-12f;
        #pragma unroll
        for (int k = 0; k < LL; k++) {
            const float dk = hi[k] - hj[k];
            d2 += dk * dk;
        }
        g_dist[bb*NN*NN + i*NN + j] = sqrtf(d2);
    }
}

// ---------------------------------------------------------------------------
// Edge MLP + aggregation — the hot kernel, rebuilt around an 8x8 register
// tile per thread so the inner loop does 64 FMA per 16 shared floats.
//
// One block per (b,i), 128 threads.
//   Phase 1: t[j][k] = lrelu(s_i[k] + v_j[k] + dist_ij * wd[k]), j-major,
//            row stride 65 (conflict-free stores AND conflict-free strided
//            reads: 8*65 % 32 == 8 -> 4 jg-groups hit 4 distinct banks).
//   Phase 2: thread (jg = tid>>3, cg = tid&7) computes the 8x8 tile
//            z[j0..j0+7][c0..c0+7] of t @ W1, then applies bias + leaky and
//            accumulates over its j's (masked to j < 100). jg >= 13 tiles are
//            fully out of range: their reads are clamped into the array and
//            their contributions fully masked.
//   Reduce 16 jg partials through smem (reusing sh_t).
// ---------------------------------------------------------------------------
#define TROWS 104         // 13 j-tiles of 8 (valid j < 100; rows 100..103 garbage/masked)
#define TS    65          // row stride: conflict-free for both access patterns

__global__ void __launch_bounds__(128) k_edge(const float* __restrict__ w0,
                                              const float* __restrict__ w1,
                                              const float* __restrict__ b1)
{
    __shared__ float sh_t [TROWS * TS];  // 27.0 KB, t[j][k]
    __shared__ float sh_w1[EH * EH];     // 16 KB, W1[k][c]
    __shared__ float sh_dist[NN];
    __shared__ float sh_s[EH], sh_wd[EH], sh_b1[EH];

    const int tid = threadIdx.x;
    const int r   = blockIdx.x;          // b*100 + i
    const int bb  = r / NN;
    const int i   = r - bb*NN;

    for (int idx = tid; idx < EH*EH; idx += 128) sh_w1[idx] = w1[idx];
    if (tid < NN) sh_dist[tid] = g_dist[bb*NN*NN + i*NN + tid];
    if (tid < EH) {
        sh_s [tid] = g_s[r*EH + tid];
        sh_wd[tid] = w0[(2*LL)*EH + tid];   // row 64 of W0: dist weights
        sh_b1[tid] = b1[tid];
    }
    __syncthreads();

    // Phase 1: layer-0 activations for all j, stored j-major (stride TS).
    // Consecutive lanes write consecutive k -> conflict-free STS; gmem reads
    // of v are fully coalesced.
    const float* vbase = &g_v[bb*NN*EH];
    for (int idx = tid; idx < NN*EH; idx += 128) {
        const int j = idx >> 6;
        const int c = idx & 63;
        const float t = sh_s[c] + vbase[idx] + sh_dist[j] * sh_wd[c];
        sh_t[j*TS + c] = lrelu(t);
    }
    __syncthreads();

    // Phase 2: 8x8 register-tiled GEMM  (padded-j x 64) = t @ W1
    const int cg = tid & 7;       // 8 col-groups of 8
    const int jg = tid >> 3;      // 16 j-groups of 8
    const int c0 = cg * 8;
    const int j0 = jg * 8;                        // logical j base (for masking)
    const int j0c = (j0 <= TROWS - 8) ? j0 : (TROWS - 8);  // clamped read base

    const float* tb = &sh_t[j0c * TS];

    float acc[8][8];
    #pragma unroll
    for (int u = 0; u < 8; u++)
        #pragma unroll
        for (int v = 0; v < 8; v++) acc[u][v] = 0.f;

    #pragma unroll 4
    for (int k = 0; k < EH; k++) {
        float tr[8];
        #pragma unroll
        for (int u = 0; u < 8; u++) tr[u] = tb[u*TS + k];
        const float4 wa = *reinterpret_cast<const float4*>(&sh_w1[k*EH + c0]);
        const float4 wb = *reinterpret_cast<const float4*>(&sh_w1[k*EH + c0 + 4]);
        #pragma unroll
        for (int u = 0; u < 8; u++) {
            acc[u][0] += tr[u] * wa.x;
            acc[u][1] += tr[u] * wa.y;
            acc[u][2] += tr[u] * wa.z;
            acc[u][3] += tr[u] * wa.w;
            acc[u][4] += tr[u] * wb.x;
            acc[u][5] += tr[u] * wb.y;
            acc[u][6] += tr[u] * wb.z;
            acc[u][7] += tr[u] * wb.w;
        }
    }

    // Epilogue: bias + leaky, accumulate over this thread's valid j's
    float bv[8];
    #pragma unroll
    for (int v = 0; v < 8; v++) bv[v] = sh_b1[c0 + v];

    float part[8];
    #pragma unroll
    for (int v = 0; v < 8; v++) part[v] = 0.f;
    #pragma unroll
    for (int u = 0; u < 8; u++) {
        if (j0 + u < NN) {
            #pragma unroll
            for (int v = 0; v < 8; v++)
                part[v] += lrelu(acc[u][v] + bv[v]);
        }
    }

    // Reduce the 16 jg partials (reuse sh_t storage — t is dead now)
    __syncthreads();
    float* red = sh_t;                 // needs 16*64 floats, fits
    #pragma unroll
    for (int v = 0; v < 8; v++) red[jg*64 + c0 + v] = part[v];
    __syncthreads();
    if (tid < EH) {
        float s = 0.f;
        #pragma unroll
        for (int g = 0; g < 16; g++) s += red[g*64 + tid];
        g_agg[r*EH + tid] = s;
    }
}

// ---------------------------------------------------------------------------
// Node MLP: h <- leaky(leaky([h, agg] @ Wn0 + bn0) @ Wn1 + bn1)
// ---------------------------------------------------------------------------
__global__ void k_node(const float* __restrict__ wn0, const float* __restrict__ bn0,
                       const float* __restrict__ wn1, const float* __restrict__ bn1)
{
    const int r = blockIdx.x;
    const int c = threadIdx.x;   // 0..63
    __shared__ float in[LL + EH];   // 96
    __shared__ float hid[NHID];
    if (c < LL) in[c] = g_h[r*LL + c];
    in[LL + c] = g_agg[r*EH + c];
    __syncthreads();
    float a = bn0[c];
    #pragma unroll
    for (int k = 0; k < LL + EH; k++)
        a += in[k] * wn0[k*NHID + c];
    hid[c] = lrelu(a);
    __syncthreads();
    if (c < NOUT) {
        float o = bn1[c];
        #pragma unroll
        for (int k = 0; k < NHID; k++)
            o += hid[k] * wn1[k*NOUT + c];
        g_h[r*LL + c] = lrelu(o);
    }
}

// ---------------------------------------------------------------------------
// Output head: out = tanh(h @ out_w + out_b), shape (B*N, 3)
// ---------------------------------------------------------------------------
__global__ void k_out(const float* __restrict__ w,
                      const float* __restrict__ b,
                      float* __restrict__ out)
{
    const int idx = blockIdx.x * blockDim.x + threadIdx.x;
    if (idx >= RR * 3) return;
    const int r = idx / 3;
    const int o = idx - r*3;
    const float* h = &g_h[r*LL];
    float a = b[o];
    #pragma unroll
    for (int k = 0; k < LL; k++)
        a += h[k] * w[k*3 + o];
    out[idx] = tanhf(a);
}

// ---------------------------------------------------------------------------
// Launch — pure kernel launches, graph-capturable, allocation-free
// ---------------------------------------------------------------------------
extern "C" void kernel_launch(void* const* d_in, const int* in_sizes, int n_in,
                              void* d_out, int out_size)
{
    const float* x  = (const float*)d_in[0];
    const float* lw = (const float*)d_in[1];
    const float* lb = (const float*)d_in[2];
    const float* ew0[2] = { (const float*)d_in[3],  (const float*)d_in[11] };
    const float* eb0[2] = { (const float*)d_in[4],  (const float*)d_in[12] };
    const float* ew1[2] = { (const float*)d_in[5],  (const float*)d_in[13] };
    const float* eb1[2] = { (const float*)d_in[6],  (const float*)d_in[14] };
    const float* nw0[2] = { (const float*)d_in[7],  (const float*)d_in[15] };
    const float* nb0[2] = { (const float*)d_in[8],  (const float*)d_in[16] };
    const float* nw1[2] = { (const float*)d_in[9],  (const float*)d_in[17] };
    const float* nb1[2] = { (const float*)d_in[10], (const float*)d_in[18] };
    const float* ow = (const float*)d_in[19];
    const float* ob = (const float*)d_in[20];

    k_lin<<<BB, 256>>>(x, lw, lb);
    for (int s = 0; s < 2; s++) {
        k_prep<<<RR, 64>>>(ew0[s], eb0[s]);
        k_dist<<<BB*4, 256>>>();
        k_edge<<<RR, 128>>>(ew0[s], ew1[s], eb1[s]);
        k_node<<<RR, 64>>>(nw0[s], nb0[s], nw1[s], nb1[s]);
    }
    k_out<<<(RR*3 + 255)/256, 256>>>(ow, ob, (float*)d_out);
}